// round 2
// baseline (speedup 1.0000x reference)
#include <cuda_runtime.h>
#include <cstdint>

// Problem constants (fixed shapes per reference)
#define N_NODES   8192
#define IN_F      1024
#define OUT_F     512
#define N_EDGES   262144
#define MASK_ROW_WORDS (N_NODES / 32)                 // 256 words per row
#define MASK_WORDS     (N_NODES * MASK_ROW_WORDS)     // 2,097,152 words = 8 MB

// Device-global scratch (allocation-free rule)
__device__ uint32_t g_mask[MASK_WORDS];
__device__ float    g_hidden[N_NODES * OUT_F];        // 16 MB, L2-resident
__device__ int      g_is64;                           // 1 if edge_index is int64

// ---------------------------------------------------------------------------
// Kernel 0: detect edge_index dtype from int32 view.
// int64 data (values < 2^31): every odd int32 element is a 0 high-word.
// int32 data: P(100 consecutive odd elements all 0) = (1/8192)^100 ~ 0.
// ---------------------------------------------------------------------------
__global__ void detect_dtype_kernel(const int* __restrict__ ei32) {
    int all_zero = 1;
    for (int i = 0; i < 100; i++) {
        if (ei32[2 * i + 1] != 0) { all_zero = 0; break; }
    }
    g_is64 = all_zero;
}

// ---------------------------------------------------------------------------
// Kernel 1: zero the adjacency bitmask (must re-zero every graph replay)
// ---------------------------------------------------------------------------
__global__ void zero_mask_kernel() {
    int idx = blockIdx.x * blockDim.x + threadIdx.x;
    uint4* p = reinterpret_cast<uint4*>(g_mask);
    int n4 = MASK_WORDS / 4;
    for (int i = idx; i < n4; i += gridDim.x * blockDim.x) {
        p[i] = make_uint4(0u, 0u, 0u, 0u);
    }
}

// ---------------------------------------------------------------------------
// Kernel 2: build adjacency bitmask from edge list (set semantics via OR)
// edge_index [2, E]: rows src, dst ; adj[src][dst] = 1
// Decodes int32 or int64 storage based on g_is64; bounds-guarded.
// ---------------------------------------------------------------------------
__global__ void build_mask_kernel(const int* __restrict__ ei32) {
    int e = blockIdx.x * blockDim.x + threadIdx.x;
    if (e >= N_EDGES) return;
    int src, dst;
    if (g_is64) {
        // int64 little-endian: low word at even int32 index
        src = ei32[2 * e];
        dst = ei32[2 * (N_EDGES + e)];
    } else {
        src = ei32[e];
        dst = ei32[N_EDGES + e];
    }
    if ((unsigned)src >= N_NODES || (unsigned)dst >= N_NODES) return;
    atomicOr(&g_mask[src * MASK_ROW_WORDS + (dst >> 5)], 1u << (dst & 31));
}

// ---------------------------------------------------------------------------
// Kernel 3: hidden = x @ W^T + b   (fp32 SIMT GEMM, 64x64 tile, 4x4/thread)
// x: [N_NODES, IN_F] row-major;  W: [OUT_F, IN_F] row-major (torch Linear)
// ---------------------------------------------------------------------------
__global__ __launch_bounds__(256) void gemm_kernel(
    const float* __restrict__ x,
    const float* __restrict__ W,
    const float* __restrict__ bias)
{
    __shared__ float As[16][64];   // [k][m]
    __shared__ float Bs[16][64];   // [k][n]

    const int bm = blockIdx.y * 64;
    const int bn = blockIdx.x * 64;
    const int tid = threadIdx.x;
    const int tx = tid & 15;       // n-quad index 0..15
    const int ty = tid >> 4;       // m-quad index 0..15

    // loader: each thread loads one float4 along k for A and B tiles
    const int lm = tid >> 2;          // 0..63 tile row
    const int lk = (tid & 3) * 4;     // 0,4,8,12

    float acc[4][4] = {};

    const float* xrow = x + (size_t)(bm + lm) * IN_F + lk;
    const float* wrow = W + (size_t)(bn + lm) * IN_F + lk;

    for (int k0 = 0; k0 < IN_F; k0 += 16) {
        float4 av = *reinterpret_cast<const float4*>(xrow + k0);
        float4 bv = *reinterpret_cast<const float4*>(wrow + k0);
        As[lk + 0][lm] = av.x; As[lk + 1][lm] = av.y;
        As[lk + 2][lm] = av.z; As[lk + 3][lm] = av.w;
        Bs[lk + 0][lm] = bv.x; Bs[lk + 1][lm] = bv.y;
        Bs[lk + 2][lm] = bv.z; Bs[lk + 3][lm] = bv.w;
        __syncthreads();

        #pragma unroll
        for (int k = 0; k < 16; k++) {
            float4 a4 = *reinterpret_cast<const float4*>(&As[k][ty * 4]);
            float4 b4 = *reinterpret_cast<const float4*>(&Bs[k][tx * 4]);
            float a[4] = {a4.x, a4.y, a4.z, a4.w};
            float b[4] = {b4.x, b4.y, b4.z, b4.w};
            #pragma unroll
            for (int i = 0; i < 4; i++)
                #pragma unroll
                for (int j = 0; j < 4; j++)
                    acc[i][j] += a[i] * b[j];
        }
        __syncthreads();
    }

    #pragma unroll
    for (int i = 0; i < 4; i++) {
        int m = bm + ty * 4 + i;
        #pragma unroll
        for (int j = 0; j < 4; j++) {
            int n = bn + tx * 4 + j;
            g_hidden[(size_t)m * OUT_F + n] = acc[i][j] + bias[n];
        }
    }
}

// ---------------------------------------------------------------------------
// Kernel 4: out[i] = relu( sum_{j: adj[i][j]} hidden[j] )
// One block per output row; 512 threads = one per output feature.
// hidden (16 MB) is L2-resident -> aggregation reads hit L2.
// ---------------------------------------------------------------------------
__global__ __launch_bounds__(OUT_F) void aggregate_kernel(float* __restrict__ out) {
    const int row = blockIdx.x;
    const int f   = threadIdx.x;
    const uint32_t* mrow = &g_mask[row * MASK_ROW_WORDS];

    float acc = 0.0f;
    for (int w = 0; w < MASK_ROW_WORDS; w++) {
        uint32_t word = mrow[w];            // uniform across warp -> broadcast
        while (word) {
            int bit = __ffs(word) - 1;
            word &= word - 1;
            int j = (w << 5) + bit;
            acc += g_hidden[(size_t)j * OUT_F + f];   // coalesced across threads
        }
    }
    out[(size_t)row * OUT_F + f] = fmaxf(acc, 0.0f);
}

// ---------------------------------------------------------------------------
// Launch
// inputs (metadata order): x[f32], W[f32], b[f32], edge_index[i32 or i64], num_nodes
// output: f32 [8192, 512]
// ---------------------------------------------------------------------------
extern "C" void kernel_launch(void* const* d_in, const int* in_sizes, int n_in,
                              void* d_out, int out_size)
{
    const float* x    = (const float*)d_in[0];
    const float* W    = (const float*)d_in[1];
    const float* bias = (const float*)d_in[2];
    const int*   ei   = (const int*)d_in[3];
    float*       out  = (float*)d_out;

    (void)in_sizes; (void)n_in; (void)out_size;

    // 0) detect edge_index dtype (int32 vs int64)
    detect_dtype_kernel<<<1, 1>>>(ei);

    // 1) zero adjacency bitmask
    zero_mask_kernel<<<1024, 256>>>();

    // 2) build bitmask from edges
    build_mask_kernel<<<N_EDGES / 256, 256>>>(ei);

    // 3) hidden = x @ W^T + b
    dim3 ggrid(OUT_F / 64, N_NODES / 64);   // (8, 128)
    gemm_kernel<<<ggrid, 256>>>(x, W, bias);

    // 4) sparse aggregation + relu
    aggregate_kernel<<<N_NODES, OUT_F>>>(out);
}

// round 3
// speedup vs baseline: 2.2520x; 2.2520x over previous
#include <cuda_runtime.h>
#include <cstdint>

// Problem constants (fixed shapes per reference)
#define N_NODES   8192
#define IN_F      1024
#define OUT_F     512
#define N_EDGES   262144
#define MASK_ROW_WORDS (N_NODES / 32)                 // 256 words per row
#define MASK_WORDS     (N_NODES * MASK_ROW_WORDS)     // 2,097,152 words = 8 MB
#define NBR_STRIDE 192                                // max stored degree (Poisson(32): P(>192) ~ 0)

// Device-global scratch (allocation-free rule)
__device__ uint32_t g_mask[MASK_WORDS];
__device__ float    g_hidden[N_NODES * OUT_F];        // 16 MB, L2-resident
__device__ uint16_t g_nbr[N_NODES * NBR_STRIDE];      // 3 MB CSR-ish neighbor lists
__device__ int      g_cnt[N_NODES];
__device__ int      g_is64;                           // 1 if edge_index is int64

// ---------------------------------------------------------------------------
// Kernel 0: detect edge_index dtype from int32 view (one warp, parallel).
// int64 data (values < 2^31): every odd int32 element is a 0 high-word.
// ---------------------------------------------------------------------------
__global__ void detect_dtype_kernel(const int* __restrict__ ei32) {
    int lane = threadIdx.x;
    int nonzero = 0;
    #pragma unroll
    for (int i = 0; i < 3; i++) {
        int idx = 2 * (lane + 32 * i) + 1;   // odd int32 positions 1..191
        if (ei32[idx] != 0) nonzero = 1;
    }
    unsigned any = __ballot_sync(0xFFFFFFFFu, nonzero);
    if (lane == 0) g_is64 = (any == 0u) ? 1 : 0;
}

// ---------------------------------------------------------------------------
// Kernel 1: zero the adjacency bitmask + per-row counters
// ---------------------------------------------------------------------------
__global__ void zero_mask_kernel() {
    int idx = blockIdx.x * blockDim.x + threadIdx.x;
    uint4* p = reinterpret_cast<uint4*>(g_mask);
    int n4 = MASK_WORDS / 4;
    for (int i = idx; i < n4; i += gridDim.x * blockDim.x) {
        p[i] = make_uint4(0u, 0u, 0u, 0u);
    }
    if (idx < N_NODES) g_cnt[idx] = 0;
}

// ---------------------------------------------------------------------------
// Kernel 2: build deduped neighbor lists from edge list.
// atomicOr returns old word: the FIRST setter of a bit appends dst to the
// row's list -> exact duplicate collapse (set semantics).
// ---------------------------------------------------------------------------
__global__ void build_mask_kernel(const int* __restrict__ ei32) {
    int e = blockIdx.x * blockDim.x + threadIdx.x;
    if (e >= N_EDGES) return;
    int src, dst;
    if (g_is64) {
        src = ei32[2 * e];                    // int64 little-endian low word
        dst = ei32[2 * (N_EDGES + e)];
    } else {
        src = ei32[e];
        dst = ei32[N_EDGES + e];
    }
    if ((unsigned)src >= N_NODES || (unsigned)dst >= N_NODES) return;
    uint32_t bit = 1u << (dst & 31);
    uint32_t old = atomicOr(&g_mask[src * MASK_ROW_WORDS + (dst >> 5)], bit);
    if (!(old & bit)) {
        int pos = atomicAdd(&g_cnt[src], 1);
        if (pos < NBR_STRIDE)
            g_nbr[src * NBR_STRIDE + pos] = (uint16_t)dst;
    }
}

// ---------------------------------------------------------------------------
// Kernel 3: hidden = x @ W^T + b   (fp32 SIMT GEMM, 64x64 tile, 4x4/thread)
// At the fp32 SIMT roofline (~253us theoretical); tensor-core target next.
// ---------------------------------------------------------------------------
__global__ __launch_bounds__(256) void gemm_kernel(
    const float* __restrict__ x,
    const float* __restrict__ W,
    const float* __restrict__ bias)
{
    __shared__ float As[16][64];   // [k][m]
    __shared__ float Bs[16][64];   // [k][n]

    const int bm = blockIdx.y * 64;
    const int bn = blockIdx.x * 64;
    const int tid = threadIdx.x;
    const int tx = tid & 15;
    const int ty = tid >> 4;

    const int lm = tid >> 2;
    const int lk = (tid & 3) * 4;

    float acc[4][4] = {};

    const float* xrow = x + (size_t)(bm + lm) * IN_F + lk;
    const float* wrow = W + (size_t)(bn + lm) * IN_F + lk;

    for (int k0 = 0; k0 < IN_F; k0 += 16) {
        float4 av = *reinterpret_cast<const float4*>(xrow + k0);
        float4 bv = *reinterpret_cast<const float4*>(wrow + k0);
        As[lk + 0][lm] = av.x; As[lk + 1][lm] = av.y;
        As[lk + 2][lm] = av.z; As[lk + 3][lm] = av.w;
        Bs[lk + 0][lm] = bv.x; Bs[lk + 1][lm] = bv.y;
        Bs[lk + 2][lm] = bv.z; Bs[lk + 3][lm] = bv.w;
        __syncthreads();

        #pragma unroll
        for (int k = 0; k < 16; k++) {
            float4 a4 = *reinterpret_cast<const float4*>(&As[k][ty * 4]);
            float4 b4 = *reinterpret_cast<const float4*>(&Bs[k][tx * 4]);
            float a[4] = {a4.x, a4.y, a4.z, a4.w};
            float b[4] = {b4.x, b4.y, b4.z, b4.w};
            #pragma unroll
            for (int i = 0; i < 4; i++)
                #pragma unroll
                for (int j = 0; j < 4; j++)
                    acc[i][j] += a[i] * b[j];
        }
        __syncthreads();
    }

    #pragma unroll
    for (int i = 0; i < 4; i++) {
        int m = bm + ty * 4 + i;
        #pragma unroll
        for (int j = 0; j < 4; j++) {
            int n = bn + tx * 4 + j;
            g_hidden[(size_t)m * OUT_F + n] = acc[i][j] + bias[n];
        }
    }
}

// ---------------------------------------------------------------------------
// Kernel 4: out[row] = relu( sum_{j in nbr[row]} hidden[j] )
// 1 block/row, 128 threads x float4 (512 features). Neighbor list staged in
// smem; 4-way unrolled gather with 4 independent accumulators (MLP >= 4).
// Gather is L2-bandwidth bound: ~512MB / ~11TB/s ~ 46us floor.
// ---------------------------------------------------------------------------
__global__ __launch_bounds__(128) void aggregate_kernel(float* __restrict__ out) {
    __shared__ uint16_t s_nbr[NBR_STRIDE];
    __shared__ int s_deg;

    const int row = blockIdx.x;
    const int col = threadIdx.x;        // float4 column 0..127

    if (col == 0) s_deg = min(g_cnt[row], NBR_STRIDE);
    __syncthreads();
    const int deg = s_deg;
    for (int i = col; i < deg; i += 128)
        s_nbr[i] = g_nbr[row * NBR_STRIDE + i];
    __syncthreads();

    const float4* H = reinterpret_cast<const float4*>(g_hidden);

    float4 a0 = make_float4(0.f, 0.f, 0.f, 0.f);
    float4 a1 = make_float4(0.f, 0.f, 0.f, 0.f);
    float4 a2 = make_float4(0.f, 0.f, 0.f, 0.f);
    float4 a3 = make_float4(0.f, 0.f, 0.f, 0.f);

    int i = 0;
    for (; i + 4 <= deg; i += 4) {
        int j0 = s_nbr[i + 0], j1 = s_nbr[i + 1];
        int j2 = s_nbr[i + 2], j3 = s_nbr[i + 3];
        float4 v0 = H[j0 * 128 + col];
        float4 v1 = H[j1 * 128 + col];
        float4 v2 = H[j2 * 128 + col];
        float4 v3 = H[j3 * 128 + col];
        a0.x += v0.x; a0.y += v0.y; a0.z += v0.z; a0.w += v0.w;
        a1.x += v1.x; a1.y += v1.y; a1.z += v1.z; a1.w += v1.w;
        a2.x += v2.x; a2.y += v2.y; a2.z += v2.z; a2.w += v2.w;
        a3.x += v3.x; a3.y += v3.y; a3.z += v3.z; a3.w += v3.w;
    }
    for (; i < deg; i++) {
        int j = s_nbr[i];
        float4 v = H[j * 128 + col];
        a0.x += v.x; a0.y += v.y; a0.z += v.z; a0.w += v.w;
    }

    float4 r;
    r.x = fmaxf(a0.x + a1.x + a2.x + a3.x, 0.f);
    r.y = fmaxf(a0.y + a1.y + a2.y + a3.y, 0.f);
    r.z = fmaxf(a0.z + a1.z + a2.z + a3.z, 0.f);
    r.w = fmaxf(a0.w + a1.w + a2.w + a3.w, 0.f);
    reinterpret_cast<float4*>(out)[row * 128 + col] = r;
}

// ---------------------------------------------------------------------------
// Launch
// inputs (metadata order): x[f32], W[f32], b[f32], edge_index[i32 or i64], num_nodes
// output: f32 [8192, 512]
// ---------------------------------------------------------------------------
extern "C" void kernel_launch(void* const* d_in, const int* in_sizes, int n_in,
                              void* d_out, int out_size)
{
    const float* x    = (const float*)d_in[0];
    const float* W    = (const float*)d_in[1];
    const float* bias = (const float*)d_in[2];
    const int*   ei   = (const int*)d_in[3];
    float*       out  = (float*)d_out;

    (void)in_sizes; (void)n_in; (void)out_size;

    detect_dtype_kernel<<<1, 32>>>(ei);
    zero_mask_kernel<<<1024, 256>>>();
    build_mask_kernel<<<N_EDGES / 256, 256>>>(ei);

    dim3 ggrid(OUT_F / 64, N_NODES / 64);   // (8, 128)
    gemm_kernel<<<ggrid, 256>>>(x, W, bias);

    aggregate_kernel<<<N_NODES, 128>>>(out);
}

// round 5
// speedup vs baseline: 4.3441x; 1.9290x over previous
#include <cuda_runtime.h>
#include <cstdint>

// Problem constants (fixed shapes per reference)
#define N_NODES   8192
#define IN_F      1024
#define OUT_F     512
#define N_EDGES   262144
#define MASK_ROW_WORDS (N_NODES / 32)
#define MASK_WORDS     (N_NODES * MASK_ROW_WORDS)     // 8 MB
#define NBR_STRIDE 192

// Device-global scratch (allocation-free rule)
__device__ uint32_t g_mask[MASK_WORDS];
__device__ float    g_hidden[N_NODES * OUT_F];        // 16 MB
__device__ uint16_t g_nbr[N_NODES * NBR_STRIDE];
__device__ int      g_cnt[N_NODES];
__device__ int      g_is64;
// bf16 hi/lo splits, packed bf16x2 per u32 along K (k-contiguous)
__device__ uint32_t g_xhi[N_NODES * (IN_F / 2)];      // 16 MB
__device__ uint32_t g_xlo[N_NODES * (IN_F / 2)];      // 16 MB
__device__ uint32_t g_whi[OUT_F * (IN_F / 2)];        // 1 MB
__device__ uint32_t g_wlo[OUT_F * (IN_F / 2)];        // 1 MB

// ---------------------------------------------------------------------------
// Graph preprocessing (unchanged from 321us kernel)
// ---------------------------------------------------------------------------
__global__ void detect_dtype_kernel(const int* __restrict__ ei32) {
    int lane = threadIdx.x;
    int nonzero = 0;
    #pragma unroll
    for (int i = 0; i < 3; i++) {
        if (ei32[2 * (lane + 32 * i) + 1] != 0) nonzero = 1;
    }
    unsigned any = __ballot_sync(0xFFFFFFFFu, nonzero);
    if (lane == 0) g_is64 = (any == 0u) ? 1 : 0;
}

__global__ void zero_mask_kernel() {
    int idx = blockIdx.x * blockDim.x + threadIdx.x;
    uint4* p = reinterpret_cast<uint4*>(g_mask);
    int n4 = MASK_WORDS / 4;
    for (int i = idx; i < n4; i += gridDim.x * blockDim.x)
        p[i] = make_uint4(0u, 0u, 0u, 0u);
    if (idx < N_NODES) g_cnt[idx] = 0;
}

__global__ void build_mask_kernel(const int* __restrict__ ei32) {
    int e = blockIdx.x * blockDim.x + threadIdx.x;
    if (e >= N_EDGES) return;
    int src, dst;
    if (g_is64) {
        src = ei32[2 * e];
        dst = ei32[2 * (N_EDGES + e)];
    } else {
        src = ei32[e];
        dst = ei32[N_EDGES + e];
    }
    if ((unsigned)src >= N_NODES || (unsigned)dst >= N_NODES) return;
    uint32_t bit = 1u << (dst & 31);
    uint32_t old = atomicOr(&g_mask[src * MASK_ROW_WORDS + (dst >> 5)], bit);
    if (!(old & bit)) {
        int pos = atomicAdd(&g_cnt[src], 1);
        if (pos < NBR_STRIDE)
            g_nbr[src * NBR_STRIDE + pos] = (uint16_t)dst;
    }
}

// ---------------------------------------------------------------------------
// fp32 -> bf16 hi/lo split (packed bf16x2: low 16 bits = even k)
// ---------------------------------------------------------------------------
__device__ __forceinline__ void split_pair(float2 v, uint32_t& hi, uint32_t& lo) {
    asm("cvt.rn.satfinite.bf16x2.f32 %0, %1, %2;" : "=r"(hi) : "f"(v.y), "f"(v.x));
    float h0 = __uint_as_float(hi << 16);
    float h1 = __uint_as_float(hi & 0xFFFF0000u);
    float r0 = v.x - h0;
    float r1 = v.y - h1;
    asm("cvt.rn.satfinite.bf16x2.f32 %0, %1, %2;" : "=r"(lo) : "f"(r1), "f"(r0));
}

__global__ void convert_x_kernel(const float* __restrict__ x) {
    int n = N_NODES * (IN_F / 2);
    const float2* x2 = reinterpret_cast<const float2*>(x);
    for (int i = blockIdx.x * blockDim.x + threadIdx.x; i < n; i += gridDim.x * blockDim.x) {
        uint32_t hi, lo;
        split_pair(x2[i], hi, lo);
        g_xhi[i] = hi;
        g_xlo[i] = lo;
    }
}

__global__ void convert_w_kernel(const float* __restrict__ W) {
    int n = OUT_F * (IN_F / 2);
    const float2* w2 = reinterpret_cast<const float2*>(W);
    for (int i = blockIdx.x * blockDim.x + threadIdx.x; i < n; i += gridDim.x * blockDim.x) {
        uint32_t hi, lo;
        split_pair(w2[i], hi, lo);
        g_whi[i] = hi;
        g_wlo[i] = lo;
    }
}

// ---------------------------------------------------------------------------
// mma.sync bf16 split GEMM:  hidden = x @ W^T + b
// CTA tile 128x64, BK=32 (bf16), 8 warps (2m x 4n), warp tile 64x16.
// Double-buffered cp.async; 80B-padded smem rows (conflict-free ldmatrix).
// ---------------------------------------------------------------------------
#define BM 128
#define BN 64
#define PAD_STRIDE 80          // bytes per 32-bf16 row (5 x 16B -> all banks)
#define ST_AH 0                // A-hi: 128 * 80 = 10240
#define ST_AL 10240            // A-lo
#define ST_BH 20480            // B-hi: 64 * 80 = 5120
#define ST_BL 25600            // B-lo
#define STAGE_SZ 30720
#define GEMM_SMEM (2 * STAGE_SZ)   // 61440 dynamic

__device__ __forceinline__ void cp16(uint32_t s, const void* g) {
    asm volatile("cp.async.cg.shared.global [%0], [%1], 16;" :: "r"(s), "l"(g) : "memory");
}

#define LDM_X4(r, addr) \
    asm volatile("ldmatrix.sync.aligned.m8n8.x4.shared.b16 {%0,%1,%2,%3}, [%4];" \
        : "=r"((r)[0]), "=r"((r)[1]), "=r"((r)[2]), "=r"((r)[3]) : "r"(addr))

#define MMA16816(c, a, b0, b1) \
    asm volatile("mma.sync.aligned.m16n8k16.row.col.f32.bf16.bf16.f32 " \
        "{%0,%1,%2,%3}, {%4,%5,%6,%7}, {%8,%9}, {%0,%1,%2,%3};" \
        : "+f"((c)[0]), "+f"((c)[1]), "+f"((c)[2]), "+f"((c)[3]) \
        : "r"((a)[0]), "r"((a)[1]), "r"((a)[2]), "r"((a)[3]), "r"(b0), "r"(b1))

__global__ __launch_bounds__(256, 2) void gemm_tc_kernel(const float* __restrict__ bias)
{
    extern __shared__ char smem[];
    const uint32_t sbase = (uint32_t)__cvta_generic_to_shared(smem);
    const int tid  = threadIdx.x;
    const int wid  = tid >> 5;
    const int lane = tid & 31;
    const int bm = blockIdx.y * BM;
    const int bn = blockIdx.x * BN;

    const int warp_m = wid >> 2;            // 0..1, 64 rows each
    const int warp_n = wid & 3;             // 0..3, 16 cols each

    float acc[4][2][4];
    #pragma unroll
    for (int i = 0; i < 4; i++)
        #pragma unroll
        for (int j = 0; j < 2; j++)
            #pragma unroll
            for (int k = 0; k < 4; k++) acc[i][j][k] = 0.f;

    // cp.async fill of one stage for K-chunk c (1536 x 16B, 6 per thread)
    auto issue = [&](int stage, int c) {
        uint32_t st = sbase + stage * STAGE_SZ;
        #pragma unroll
        for (int t = 0; t < 6; t++) {
            int i = tid + t * 256;
            if (i < 1024) {                              // A tiles
                int half = i >> 9;                       // 0=hi 1=lo
                int idx = i & 511;
                int row = idx >> 2, seg = idx & 3;
                const uint32_t* gsrc = (half ? g_xlo : g_xhi)
                    + (size_t)(bm + row) * (IN_F / 2) + c * 16 + seg * 4;
                cp16(st + (half ? ST_AL : ST_AH) + row * PAD_STRIDE + seg * 16, gsrc);
            } else {                                     // B tiles
                int j = i - 1024;
                int half = j >> 8;
                int idx = j & 255;
                int row = idx >> 2, seg = idx & 3;
                const uint32_t* gsrc = (half ? g_wlo : g_whi)
                    + (size_t)(bn + row) * (IN_F / 2) + c * 16 + seg * 4;
                cp16(st + (half ? ST_BL : ST_BH) + row * PAD_STRIDE + seg * 16, gsrc);
            }
        }
        asm volatile("cp.async.commit_group;" ::: "memory");
    };

    // ldmatrix per-thread source rows
    const int a_row  = warp_m * 64 + (lane & 15);     // + im*16
    const int a_half = lane >> 4;                     // k byte-half
    const int b_row  = warp_n * 16 + ((lane & 16) >> 1) + (lane & 7);
    const int b_half = (lane >> 3) & 1;

    issue(0, 0);

    const int NCHUNK = IN_F / 32;   // 32
    for (int c = 0; c < NCHUNK; c++) {
        if (c + 1 < NCHUNK) {
            issue((c + 1) & 1, c + 1);
            asm volatile("cp.async.wait_group 1;" ::: "memory");
        } else {
            asm volatile("cp.async.wait_group 0;" ::: "memory");
        }
        __syncthreads();

        const uint32_t st = sbase + (c & 1) * STAGE_SZ;
        #pragma unroll
        for (int ks = 0; ks < 2; ks++) {
            const int kb = ks * 32;                   // 16 bf16 = 32 bytes
            uint32_t ah[4][4], al[4][4];
            #pragma unroll
            for (int im = 0; im < 4; im++) {
                uint32_t addr = st + ST_AH + (a_row + im * 16) * PAD_STRIDE + kb + a_half * 16;
                LDM_X4(ah[im], addr);
                LDM_X4(al[im], addr + (ST_AL - ST_AH));
            }
            uint32_t bh[4], bl[4];
            {
                uint32_t addr = st + ST_BH + b_row * PAD_STRIDE + kb + b_half * 16;
                LDM_X4(bh, addr);
                LDM_X4(bl, addr + (ST_BL - ST_BH));
            }
            #pragma unroll
            for (int im = 0; im < 4; im++) {
                #pragma unroll
                for (int in = 0; in < 2; in++) {
                    MMA16816(acc[im][in], ah[im], bh[in * 2], bh[in * 2 + 1]); // hh
                    MMA16816(acc[im][in], ah[im], bl[in * 2], bl[in * 2 + 1]); // hl
                    MMA16816(acc[im][in], al[im], bh[in * 2], bh[in * 2 + 1]); // lh
                }
            }
        }
        __syncthreads();
    }

    // Epilogue: add bias, store fp32 hidden
    const int er = lane >> 2;
    const int ec = (lane & 3) * 2;
    #pragma unroll
    for (int im = 0; im < 4; im++) {
        int r0 = bm + warp_m * 64 + im * 16 + er;
        #pragma unroll
        for (int in = 0; in < 2; in++) {
            int col = bn + warp_n * 16 + in * 8 + ec;
            float b0 = __ldg(&bias[col]);
            float b1 = __ldg(&bias[col + 1]);
            float2 v0 = make_float2(acc[im][in][0] + b0, acc[im][in][1] + b1);
            float2 v1 = make_float2(acc[im][in][2] + b0, acc[im][in][3] + b1);
            *reinterpret_cast<float2*>(&g_hidden[(size_t)r0 * OUT_F + col]) = v0;
            *reinterpret_cast<float2*>(&g_hidden[(size_t)(r0 + 8) * OUT_F + col]) = v1;
        }
    }
}

// ---------------------------------------------------------------------------
// out[row] = relu( sum_{j in nbr[row]} hidden[j] )  (unchanged)
// ---------------------------------------------------------------------------
__global__ __launch_bounds__(128) void aggregate_kernel(float* __restrict__ out) {
    __shared__ uint16_t s_nbr[NBR_STRIDE];
    __shared__ int s_deg;

    const int row = blockIdx.x;
    const int col = threadIdx.x;

    if (col == 0) s_deg = min(g_cnt[row], NBR_STRIDE);
    __syncthreads();
    const int deg = s_deg;
    for (int i = col; i < deg; i += 128)
        s_nbr[i] = g_nbr[row * NBR_STRIDE + i];
    __syncthreads();

    const float4* H = reinterpret_cast<const float4*>(g_hidden);

    float4 a0 = make_float4(0.f, 0.f, 0.f, 0.f);
    float4 a1 = make_float4(0.f, 0.f, 0.f, 0.f);
    float4 a2 = make_float4(0.f, 0.f, 0.f, 0.f);
    float4 a3 = make_float4(0.f, 0.f, 0.f, 0.f);

    int i = 0;
    for (; i + 4 <= deg; i += 4) {
        int j0 = s_nbr[i + 0], j1 = s_nbr[i + 1];
        int j2 = s_nbr[i + 2], j3 = s_nbr[i + 3];
        float4 v0 = H[j0 * 128 + col];
        float4 v1 = H[j1 * 128 + col];
        float4 v2 = H[j2 * 128 + col];
        float4 v3 = H[j3 * 128 + col];
        a0.x += v0.x; a0.y += v0.y; a0.z += v0.z; a0.w += v0.w;
        a1.x += v1.x; a1.y += v1.y; a1.z += v1.z; a1.w += v1.w;
        a2.x += v2.x; a2.y += v2.y; a2.z += v2.z; a2.w += v2.w;
        a3.x += v3.x; a3.y += v3.y; a3.z += v3.z; a3.w += v3.w;
    }
    for (; i < deg; i++) {
        int j = s_nbr[i];
        float4 v = H[j * 128 + col];
        a0.x += v.x; a0.y += v.y; a0.z += v.z; a0.w += v.w;
    }

    float4 r;
    r.x = fmaxf(a0.x + a1.x + a2.x + a3.x, 0.f);
    r.y = fmaxf(a0.y + a1.y + a2.y + a3.y, 0.f);
    r.z = fmaxf(a0.z + a1.z + a2.z + a3.z, 0.f);
    r.w = fmaxf(a0.w + a1.w + a2.w + a3.w, 0.f);
    reinterpret_cast<float4*>(out)[row * 128 + col] = r;
}

// ---------------------------------------------------------------------------
// Launch
// ---------------------------------------------------------------------------
extern "C" void kernel_launch(void* const* d_in, const int* in_sizes, int n_in,
                              void* d_out, int out_size)
{
    const float* x    = (const float*)d_in[0];
    const float* W    = (const float*)d_in[1];
    const float* bias = (const float*)d_in[2];
    const int*   ei   = (const int*)d_in[3];
    float*       out  = (float*)d_out;

    (void)in_sizes; (void)n_in; (void)out_size;

    cudaFuncSetAttribute(gemm_tc_kernel,
                         cudaFuncAttributeMaxDynamicSharedMemorySize, GEMM_SMEM);

    detect_dtype_kernel<<<1, 32>>>(ei);
    zero_mask_kernel<<<1024, 256>>>();
    build_mask_kernel<<<N_EDGES / 256, 256>>>(ei);

    convert_x_kernel<<<2048, 256>>>(x);
    convert_w_kernel<<<512, 256>>>(W);

    dim3 ggrid(OUT_F / BN, N_NODES / BM);   // (8, 64)
    gemm_tc_kernel<<<ggrid, 256, GEMM_SMEM>>>(bias);

    aggregate_kernel<<<N_NODES, 128>>>(out);
}